// round 9
// baseline (speedup 1.0000x reference)
#include <cuda_runtime.h>
#include <stdint.h>
#include <math.h>

#define NN   256
#define CZ   128
#define H    4
#define DH   32
#define NPOS (NN*NN)

// Scratch (device globals; device-code access only).
__device__ __align__(16) uint32_t g_xn[NPOS*CZ];
__device__ __align__(16) uint32_t g_q [NPOS*CZ];
__device__ __align__(16) uint32_t g_k [NPOS*CZ];
__device__ __align__(16) uint32_t g_v [NPOS*CZ];
__device__ __align__(16) float    g_g [NPOS*CZ];
__device__ __align__(16) uint32_t g_o [NPOS*CZ];
__device__ __align__(16) float    g_tri[H*NPOS];       // tri * log2e
__device__ __align__(16) uint32_t g_wt[5*CZ*CZ];       // wq*scale*log2e, wk, wv, wg, wo

#define LOG2E 1.4426950408889634f

// ---- helpers ---------------------------------------------------------------
__device__ __forceinline__ uint32_t f2tf32(float f) {
    uint32_t u;
    asm("cvt.rna.tf32.f32 %0, %1;" : "=r"(u) : "f"(f));
    return u;
}
__device__ __forceinline__ float ex2f(float x) {
    float y;
    asm("ex2.approx.f32 %0, %1;" : "=f"(y) : "f"(x));
    return y;
}
__device__ __forceinline__ void mma_tf32(float* d, const uint32_t* a, const uint32_t* b) {
    asm volatile(
        "mma.sync.aligned.m16n8k8.row.col.f32.tf32.tf32.f32 "
        "{%0,%1,%2,%3}, {%4,%5,%6,%7}, {%8,%9}, {%0,%1,%2,%3};"
        : "+f"(d[0]), "+f"(d[1]), "+f"(d[2]), "+f"(d[3])
        : "r"(a[0]), "r"(a[1]), "r"(a[2]), "r"(a[3]),
          "r"(b[0]), "r"(b[1]));
}
__device__ __forceinline__ void cp16(uint32_t* smem_dst, const uint32_t* gsrc) {
    uint32_t sa = (uint32_t)__cvta_generic_to_shared(smem_dst);
    asm volatile("cp.async.ca.shared.global [%0], [%1], 16;"
                 :: "r"(sa), "l"(gsrc) : "memory");
}
#define CP_COMMIT() asm volatile("cp.async.commit_group;" ::: "memory")
#define CP_WAIT0()  asm volatile("cp.async.wait_group 0;" ::: "memory")

// ---------------------------------------------------------------------------
// K0: weight prep — 5 weight matrices to tf32 (wq folded with scale*log2e)
// ---------------------------------------------------------------------------
__global__ __launch_bounds__(256) void k_prep(
    const float* __restrict__ wq, const float* __restrict__ wk,
    const float* __restrict__ wv, const float* __restrict__ wg,
    const float* __restrict__ wo)
{
    int sel = blockIdx.y;
    int idx = blockIdx.x * 256 + threadIdx.x;
    const float* src = (sel==0) ? wq : (sel==1) ? wk : (sel==2) ? wv
                     : (sel==3) ? wg : wo;
    float v = src[idx];
    if (sel == 0) v *= 0.17677669529663687f * LOG2E;   // 1/sqrt(DH) * log2(e)
    g_wt[sel*CZ*CZ + idx] = f2tf32(v);
}

// ---------------------------------------------------------------------------
// K1: LayerNorm (warp per position) + fused triangle bias (stored * log2e)
// ---------------------------------------------------------------------------
__global__ __launch_bounds__(256) void k_ln(
    const float* __restrict__ x,
    const float* __restrict__ ln_g,
    const float* __restrict__ ln_b,
    const float* __restrict__ w_tri)
{
    int warp = threadIdx.x >> 5;
    int lane = threadIdx.x & 31;
    int pos  = blockIdx.x * 8 + warp;

    float4 v = *(const float4*)(x + (size_t)pos*CZ + lane*4);
    float s  = v.x + v.y + v.z + v.w;
    float ss = v.x*v.x + v.y*v.y + v.z*v.z + v.w*v.w;
    #pragma unroll
    for (int off = 16; off; off >>= 1) {
        s  += __shfl_xor_sync(0xffffffffu, s,  off);
        ss += __shfl_xor_sync(0xffffffffu, ss, off);
    }
    float mu  = s * (1.0f/CZ);
    float var = ss * (1.0f/CZ) - mu*mu;
    float rs  = rsqrtf(var + 1e-5f);

    float4 gg = *(const float4*)(ln_g + lane*4);
    float4 bb = *(const float4*)(ln_b + lane*4);
    float4 y;
    y.x = (v.x - mu)*rs*gg.x + bb.x;
    y.y = (v.y - mu)*rs*gg.y + bb.y;
    y.z = (v.z - mu)*rs*gg.z + bb.z;
    y.w = (v.w - mu)*rs*gg.w + bb.w;
    uint4 u;
    u.x = f2tf32(y.x); u.y = f2tf32(y.y);
    u.z = f2tf32(y.z); u.w = f2tf32(y.w);
    *(uint4*)(g_xn + (size_t)pos*CZ + lane*4) = u;

    #pragma unroll
    for (int h = 0; h < H; h++) {
        float4 w = *(const float4*)(w_tri + h*CZ + lane*4);
        float d = y.x*w.x + y.y*w.y + y.z*w.z + y.w*w.w;
        #pragma unroll
        for (int off = 16; off; off >>= 1)
            d += __shfl_xor_sync(0xffffffffu, d, off);
        if (lane == 0) g_tri[h*NPOS + pos] = d * LOG2E;
    }
}

// ---------------------------------------------------------------------------
// tf32 GEMM 128x128, 8 warps, cp.async double buffer (verified)
// ---------------------------------------------------------------------------
#define GSTG (128*36)

__device__ __forceinline__ void gemm_stage(
    const uint32_t* __restrict__ A, const uint32_t* __restrict__ W,
    uint32_t* as, uint32_t* ws, int p0, int c0, int t)
{
    #pragma unroll
    for (int i = 0; i < 4; i++) {
        int idx = t + i*256;
        int row = idx >> 3;
        int cs  = idx & 7;
        cp16(as + row*36 + cs*4, A + (size_t)(p0+row)*CZ + c0 + cs*4);
        cp16(ws + row*36 + cs*4, W + (size_t)row*CZ + c0 + cs*4);
    }
}

__device__ __forceinline__ void gemm_tile(
    const uint32_t* __restrict__ A,
    const uint32_t* __restrict__ W,
    float* __restrict__ outf,
    uint32_t* __restrict__ outt,
    const float* __restrict__ bias,
    int act, int p0)
{
    extern __shared__ uint32_t dyn[];
    int t    = threadIdx.x;
    int warp = t >> 5;
    int lane = t & 31;
    int gq   = lane >> 2;
    int tq   = lane & 3;
    int wm   = (warp >> 2) * 64;
    int wn   = (warp & 3) * 32;

    float acc[4][4][4];
    #pragma unroll
    for (int mi = 0; mi < 4; mi++)
        #pragma unroll
        for (int ni = 0; ni < 4; ni++)
            #pragma unroll
            for (int r = 0; r < 4; r++) acc[mi][ni][r] = 0.0f;

    gemm_stage(A, W, dyn, dyn + 2*GSTG, p0, 0, t);
    CP_COMMIT();
    CP_WAIT0();
    __syncthreads();

    for (int c = 0; c < 4; c++) {
        if (c < 3) {
            int nb = (c+1) & 1;
            gemm_stage(A, W, dyn + nb*GSTG, dyn + 2*GSTG + nb*GSTG,
                       p0, (c+1)*32, t);
            CP_COMMIT();
        }
        const uint32_t* as = dyn + (c&1)*GSTG;
        const uint32_t* ws = dyn + 2*GSTG + (c&1)*GSTG;

        #pragma unroll
        for (int ks = 0; ks < 4; ks++) {
            int kb = ks * 8;
            uint32_t afr[4][4], bfr[4][2];
            #pragma unroll
            for (int mi = 0; mi < 4; mi++) {
                int r = wm + mi*16 + gq;
                afr[mi][0] = as[r*36     + kb+tq];
                afr[mi][1] = as[(r+8)*36 + kb+tq];
                afr[mi][2] = as[r*36     + kb+tq+4];
                afr[mi][3] = as[(r+8)*36 + kb+tq+4];
            }
            #pragma unroll
            for (int ni = 0; ni < 4; ni++) {
                int n = wn + ni*8 + gq;
                bfr[ni][0] = ws[n*36 + kb+tq];
                bfr[ni][1] = ws[n*36 + kb+tq+4];
            }
            #pragma unroll
            for (int mi = 0; mi < 4; mi++)
                #pragma unroll
                for (int ni = 0; ni < 4; ni++)
                    mma_tf32(acc[mi][ni], afr[mi], bfr[ni]);
        }
        if (c < 3) {
            CP_WAIT0();
            __syncthreads();
        }
    }

    #pragma unroll
    for (int mi = 0; mi < 4; mi++) {
        #pragma unroll
        for (int ni = 0; ni < 4; ni++) {
            int col = wn + ni*8 + tq*2;
            float b0 = 0.f, b1 = 0.f;
            if (act) { b0 = bias[col]; b1 = bias[col+1]; }
            #pragma unroll
            for (int rr = 0; rr < 2; rr++) {
                int pos = p0 + wm + mi*16 + gq + rr*8;
                float vx = acc[mi][ni][rr*2+0];
                float vy = acc[mi][ni][rr*2+1];
                if (act == 0) {
                    *(uint2*)(outt + (size_t)pos*CZ + col) =
                        make_uint2(f2tf32(vx), f2tf32(vy));
                } else if (act == 1) {
                    vx = 1.0f/(1.0f + __expf(-(vx + b0)));
                    vy = 1.0f/(1.0f + __expf(-(vy + b1)));
                    *(float2*)(outf + (size_t)pos*CZ + col) = make_float2(vx, vy);
                } else {
                    *(float2*)(outf + (size_t)pos*CZ + col) =
                        make_float2(vx + b0, vy + b1);
                }
            }
        }
    }
}

__global__ __launch_bounds__(256, 2) void k_proj(const float* __restrict__ bg)
{
    int sel = blockIdx.y;
    const uint32_t* W = g_wt + (size_t)sel*CZ*CZ;
    uint32_t* outt = (sel==0) ? g_q : (sel==1) ? g_k : (sel==2) ? g_v : nullptr;
    gemm_tile(g_xn, W, g_g, outt, bg, (sel==3) ? 1 : 0, blockIdx.x * 128);
}

__global__ __launch_bounds__(256, 2) void k_outp(
    const float* __restrict__ bo, float* __restrict__ out)
{
    gemm_tile(g_o, g_wt + (size_t)4*CZ*CZ, out, nullptr, bo, 2, blockIdx.x * 128);
}

// ---------------------------------------------------------------------------
// K3: tensor-core attention v3.
// CTA = 128 threads (4 warps x 32 q-rows), grid (NN, 2, H).
// log2e pre-folded (wq, tri, mask): p = ex2(sacc + trix + mbx), no max-sub.
// P routed through per-warp smem [32][68] (no shuffles, conflict-free frags).
// ---------------------------------------------------------------------------
#define KVSTG (64*36)
#define PSTRIDE 68
#define PWARP (32*PSTRIDE)
// dynamic smem: K[2]+V[2] (4*KVSTG) + P per warp (4*PWARP)
#define ATTN_SMEM ((4*KVSTG + 4*PWARP)*4)

__global__ __launch_bounds__(128, 3) void k_attn(const float* __restrict__ mask)
{
    extern __shared__ uint32_t abuf[];
    __shared__ float mb_s[256];

    int i  = blockIdx.x;
    int q0 = blockIdx.y * 128;
    int h  = blockIdx.z;
    int t = threadIdx.x;
    int warp = t >> 5, lane = t & 31;
    int gq = lane >> 2, tq = lane & 3;
    int wrow = q0 + warp * 32;

    mb_s[t]       = LOG2E * 1e9f * (mask[i*NN + t] - 1.0f);
    mb_s[t + 128] = LOG2E * 1e9f * (mask[i*NN + t + 128] - 1.0f);

    uint32_t* kb[2] = { abuf,           abuf + KVSTG };
    uint32_t* vb[2] = { abuf + 2*KVSTG, abuf + 3*KVSTG };
    uint32_t* pw    = abuf + 4*KVSTG + warp*PWARP;   // per-warp P tile

    // stage K/V for jb=0
    #pragma unroll
    for (int it = 0; it < 4; it++) {
        int idx = t + it*128;            // 0..511
        int row = idx >> 3, c4 = idx & 7;
        size_t gb = ((size_t)(i*NN + row))*CZ + h*DH + c4*4;
        cp16(&kb[0][row*36 + c4*4], g_k + gb);
        cp16(&vb[0][row*36 + c4*4], g_v + gb);
    }
    CP_COMMIT();

    // Q fragments via direct LDG (scale*log2e folded into wq)
    uint32_t qf[2][4][4];
    #pragma unroll
    for (int mi = 0; mi < 2; mi++) {
        const uint32_t* qr0 = g_q + ((size_t)(i*NN + wrow + mi*16 + gq))*CZ + h*DH;
        const uint32_t* qr8 = qr0 + 8*CZ;
        #pragma unroll
        for (int ks = 0; ks < 4; ks++) {
            qf[mi][ks][0] = qr0[ks*8 + tq];
            qf[mi][ks][1] = qr8[ks*8 + tq];
            qf[mi][ks][2] = qr0[ks*8 + tq + 4];
            qf[mi][ks][3] = qr8[ks*8 + tq + 4];
        }
    }

    float lrun[2][2] = {{0.f,0.f},{0.f,0.f}};
    float oacc[2][4][4];
    #pragma unroll
    for (int mi = 0; mi < 2; mi++)
        #pragma unroll
        for (int nd = 0; nd < 4; nd++)
            #pragma unroll
            for (int r = 0; r < 4; r++) oacc[mi][nd][r] = 0.0f;

    const float* trib = g_tri + (size_t)h*NPOS;

    CP_WAIT0();
    __syncthreads();

    for (int jb = 0; jb < 4; jb++) {
        int j0 = jb * 64;
        int cur = jb & 1;
        if (jb < 3) {
            int nxt = (jb+1) & 1;
            #pragma unroll
            for (int it = 0; it < 4; it++) {
                int idx = t + it*128;
                int row = idx >> 3, c4 = idx & 7;
                size_t gb = ((size_t)(i*NN + j0 + 64 + row))*CZ + h*DH + c4*4;
                cp16(&kb[nxt][row*36 + c4*4], g_k + gb);
                cp16(&vb[nxt][row*36 + c4*4], g_v + gb);
            }
            CP_COMMIT();
        }
        const uint32_t* k_s = kb[cur];
        const uint32_t* v_s = vb[cur];

        // S = Q K^T (already scaled by 1/sqrt(DH)*log2e via wq)
        float sacc[2][8][4];
        #pragma unroll
        for (int mi = 0; mi < 2; mi++)
            #pragma unroll
            for (int ni = 0; ni < 8; ni++)
                #pragma unroll
                for (int r = 0; r < 4; r++) sacc[mi][ni][r] = 0.0f;

        #pragma unroll
        for (int ks = 0; ks < 4; ks++) {
            uint32_t bf[8][2];
            #pragma unroll
            for (int ni = 0; ni < 8; ni++) {
                int base = (ni*8 + gq)*36 + ks*8 + tq;
                bf[ni][0] = k_s[base];
                bf[ni][1] = k_s[base + 4];
            }
            #pragma unroll
            for (int mi = 0; mi < 2; mi++)
                #pragma unroll
                for (int ni = 0; ni < 8; ni++)
                    mma_tf32(sacc[mi][ni], qf[mi][ks], bf[ni]);
        }

        // p = ex2(sacc + trix + mbx); store P to per-warp smem; accumulate l
        #pragma unroll
        for (int mi = 0; mi < 2; mi++) {
            int r0 = wrow + mi*16 + gq;
            float la0 = 0.f, la1 = 0.f;
            #pragma unroll
            for (int ni = 0; ni < 8; ni++) {
                int j = j0 + ni*8 + tq*2;
                float2 t0 = *(const float2*)(trib + (size_t)r0*NN + j);
                float2 t1 = *(const float2*)(trib + (size_t)(r0+8)*NN + j);
                float mb0 = mb_s[j], mb1 = mb_s[j+1];
                float p0 = ex2f(sacc[mi][ni][0] + (t0.x + mb0));
                float p1 = ex2f(sacc[mi][ni][1] + (t0.y + mb1));
                float p2 = ex2f(sacc[mi][ni][2] + (t1.x + mb0));
                float p3 = ex2f(sacc[mi][ni][3] + (t1.y + mb1));
                uint32_t u0 = f2tf32(p0), u1 = f2tf32(p1);
                uint32_t u2 = f2tf32(p2), u3 = f2tf32(p3);
                int pr0 = (mi*16 + gq)*PSTRIDE + ni*8 + tq*2;
                *(uint2*)&pw[pr0]             = make_uint2(u0, u1);
                *(uint2*)&pw[pr0 + 8*PSTRIDE] = make_uint2(u2, u3);
                la0 += __uint_as_float(u0) + __uint_as_float(u1);
                la1 += __uint_as_float(u2) + __uint_as_float(u3);
            }
            lrun[mi][0] += la0; lrun[mi][1] += la1;
        }
        __syncwarp();

        // O += P V  (A-frags straight from per-warp P smem; bank = 4*gq+tq)
        #pragma unroll
        for (int ks2 = 0; ks2 < 8; ks2++) {
            uint32_t bf[4][2];
            #pragma unroll
            for (int nd = 0; nd < 4; nd++) {
                bf[nd][0] = v_s[(ks2*8 + tq)*36     + nd*8 + gq];
                bf[nd][1] = v_s[(ks2*8 + tq + 4)*36 + nd*8 + gq];
            }
            #pragma unroll
            for (int mi = 0; mi < 2; mi++) {
                int pr = (mi*16 + gq)*PSTRIDE + ks2*8;
                uint32_t af[4];
                af[0] = pw[pr + tq];
                af[1] = pw[pr + 8*PSTRIDE + tq];
                af[2] = pw[pr + tq + 4];
                af[3] = pw[pr + 8*PSTRIDE + tq + 4];
                #pragma unroll
                for (int nd = 0; nd < 4; nd++)
                    mma_tf32(oacc[mi][nd], af, bf[nd]);
            }
        }
        if (jb < 3) {
            CP_WAIT0();
            __syncthreads();
        }
    }

    // epilogue: normalize, gate, store tf32
    #pragma unroll
    for (int mi = 0; mi < 2; mi++) {
        float l0 = lrun[mi][0];
        l0 += __shfl_xor_sync(0xffffffffu, l0, 1);
        l0 += __shfl_xor_sync(0xffffffffu, l0, 2);
        float l1 = lrun[mi][1];
        l1 += __shfl_xor_sync(0xffffffffu, l1, 1);
        l1 += __shfl_xor_sync(0xffffffffu, l1, 2);
        float inv0 = 1.0f / l0, inv1 = 1.0f / l1;
        int r0 = wrow + mi*16 + gq;
        #pragma unroll
        for (int nd = 0; nd < 4; nd++) {
            int d = h*DH + nd*8 + tq*2;
            size_t b0 = ((size_t)(i*NN + r0))*CZ + d;
            size_t b1 = ((size_t)(i*NN + r0 + 8))*CZ + d;
            float2 gg0 = *(const float2*)(g_g + b0);
            float2 gg1 = *(const float2*)(g_g + b1);
            *(uint2*)(g_o + b0) = make_uint2(
                f2tf32(oacc[mi][nd][0]*inv0*gg0.x),
                f2tf32(oacc[mi][nd][1]*inv0*gg0.y));
            *(uint2*)(g_o + b1) = make_uint2(
                f2tf32(oacc[mi][nd][2]*inv1*gg1.x),
                f2tf32(oacc[mi][nd][3]*inv1*gg1.y));
        }
    }
}

// ---------------------------------------------------------------------------
extern "C" void kernel_launch(void* const* d_in, const int* in_sizes, int n_in,
                              void* d_out, int out_size)
{
    const float* x     = (const float*)d_in[0];
    const float* mask  = (const float*)d_in[1];
    const float* ln_g  = (const float*)d_in[2];
    const float* ln_b  = (const float*)d_in[3];
    const float* w_tri = (const float*)d_in[4];
    const float* wq    = (const float*)d_in[5];
    const float* wk    = (const float*)d_in[6];
    const float* wv    = (const float*)d_in[7];
    const float* wg    = (const float*)d_in[8];
    const float* bg    = (const float*)d_in[9];
    const float* wo    = (const float*)d_in[10];
    const float* bo    = (const float*)d_in[11];
    float* out = (float*)d_out;

    const int GEMM_SMEM = 4*GSTG*4;   // 73728 B
    cudaFuncSetAttribute(k_proj, cudaFuncAttributeMaxDynamicSharedMemorySize, GEMM_SMEM);
    cudaFuncSetAttribute(k_outp, cudaFuncAttributeMaxDynamicSharedMemorySize, GEMM_SMEM);
    cudaFuncSetAttribute(k_attn, cudaFuncAttributeMaxDynamicSharedMemorySize, ATTN_SMEM);

    k_prep<<<dim3(64, 5), 256>>>(wq, wk, wv, wg, wo);
    k_ln  <<<NPOS/8, 256>>>(x, ln_g, ln_b, w_tri);
    k_proj<<<dim3(NPOS/128, 4), 256, GEMM_SMEM>>>(bg);
    k_attn<<<dim3(NN, 2, H), 128, ATTN_SMEM>>>(mask);
    k_outp<<<NPOS/128, 256, GEMM_SMEM>>>(bo, out);
}

// round 10
// speedup vs baseline: 1.1029x; 1.1029x over previous
#include <cuda_runtime.h>
#include <stdint.h>
#include <math.h>

#define NN   256
#define CZ   128
#define H    4
#define DH   32
#define NPOS (NN*NN)

// Scratch (device globals; device-code access only).
__device__ __align__(16) uint32_t g_xn[NPOS*CZ];
__device__ __align__(16) uint32_t g_q [NPOS*CZ];
__device__ __align__(16) uint32_t g_k [NPOS*CZ];
__device__ __align__(16) uint32_t g_v [NPOS*CZ];
__device__ __align__(16) float    g_g [NPOS*CZ];
__device__ __align__(16) uint32_t g_o [NPOS*CZ];
__device__ __align__(16) float    g_tri [H*NPOS];      // tri * log2e (row layout)
__device__ __align__(16) float    g_trif[H*NPOS];      // fragment-permuted tri
__device__ __align__(16) uint32_t g_wt[5*CZ*CZ];       // wq*scale*log2e, wk, wv, wg, wo

#define LOG2E 1.4426950408889634f

// ---- helpers ---------------------------------------------------------------
__device__ __forceinline__ uint32_t f2tf32(float f) {
    uint32_t u;
    asm("cvt.rna.tf32.f32 %0, %1;" : "=r"(u) : "f"(f));
    return u;
}
__device__ __forceinline__ float ex2f(float x) {
    float y;
    asm("ex2.approx.f32 %0, %1;" : "=f"(y) : "f"(x));
    return y;
}
__device__ __forceinline__ void mma_tf32(float* d, const uint32_t* a, const uint32_t* b) {
    asm volatile(
        "mma.sync.aligned.m16n8k8.row.col.f32.tf32.tf32.f32 "
        "{%0,%1,%2,%3}, {%4,%5,%6,%7}, {%8,%9}, {%0,%1,%2,%3};"
        : "+f"(d[0]), "+f"(d[1]), "+f"(d[2]), "+f"(d[3])
        : "r"(a[0]), "r"(a[1]), "r"(a[2]), "r"(a[3]),
          "r"(b[0]), "r"(b[1]));
}
__device__ __forceinline__ void cp16(uint32_t* smem_dst, const uint32_t* gsrc) {
    uint32_t sa = (uint32_t)__cvta_generic_to_shared(smem_dst);
    asm volatile("cp.async.ca.shared.global [%0], [%1], 16;"
                 :: "r"(sa), "l"(gsrc) : "memory");
}
#define CP_COMMIT() asm volatile("cp.async.commit_group;" ::: "memory")
#define CP_WAIT0()  asm volatile("cp.async.wait_group 0;" ::: "memory")

// ---------------------------------------------------------------------------
// K0: weight prep — 5 weight matrices to tf32 (wq folded with scale*log2e)
// ---------------------------------------------------------------------------
__global__ __launch_bounds__(256) void k_prep(
    const float* __restrict__ wq, const float* __restrict__ wk,
    const float* __restrict__ wv, const float* __restrict__ wg,
    const float* __restrict__ wo)
{
    int sel = blockIdx.y;
    int idx = blockIdx.x * 256 + threadIdx.x;
    const float* src = (sel==0) ? wq : (sel==1) ? wk : (sel==2) ? wv
                     : (sel==3) ? wg : wo;
    float v = src[idx];
    if (sel == 0) v *= 0.17677669529663687f * LOG2E;   // 1/sqrt(DH) * log2(e)
    g_wt[sel*CZ*CZ + idx] = f2tf32(v);
}

// ---------------------------------------------------------------------------
// K1: LayerNorm (warp per position) + fused triangle bias (stored * log2e)
// ---------------------------------------------------------------------------
__global__ __launch_bounds__(256) void k_ln(
    const float* __restrict__ x,
    const float* __restrict__ ln_g,
    const float* __restrict__ ln_b,
    const float* __restrict__ w_tri)
{
    int warp = threadIdx.x >> 5;
    int lane = threadIdx.x & 31;
    int pos  = blockIdx.x * 8 + warp;

    float4 v = *(const float4*)(x + (size_t)pos*CZ + lane*4);
    float s  = v.x + v.y + v.z + v.w;
    float ss = v.x*v.x + v.y*v.y + v.z*v.z + v.w*v.w;
    #pragma unroll
    for (int off = 16; off; off >>= 1) {
        s  += __shfl_xor_sync(0xffffffffu, s,  off);
        ss += __shfl_xor_sync(0xffffffffu, ss, off);
    }
    float mu  = s * (1.0f/CZ);
    float var = ss * (1.0f/CZ) - mu*mu;
    float rs  = rsqrtf(var + 1e-5f);

    float4 gg = *(const float4*)(ln_g + lane*4);
    float4 bb = *(const float4*)(ln_b + lane*4);
    float4 y;
    y.x = (v.x - mu)*rs*gg.x + bb.x;
    y.y = (v.y - mu)*rs*gg.y + bb.y;
    y.z = (v.z - mu)*rs*gg.z + bb.z;
    y.w = (v.w - mu)*rs*gg.w + bb.w;
    uint4 u;
    u.x = f2tf32(y.x); u.y = f2tf32(y.y);
    u.z = f2tf32(y.z); u.w = f2tf32(y.w);
    *(uint4*)(g_xn + (size_t)pos*CZ + lane*4) = u;

    #pragma unroll
    for (int h = 0; h < H; h++) {
        float4 w = *(const float4*)(w_tri + h*CZ + lane*4);
        float d = y.x*w.x + y.y*w.y + y.z*w.z + y.w*w.w;
        #pragma unroll
        for (int off = 16; off; off >>= 1)
            d += __shfl_xor_sync(0xffffffffu, d, off);
        if (lane == 0) g_tri[h*NPOS + pos] = d * LOG2E;
    }
}

// ---------------------------------------------------------------------------
// K1b: permute tri into per-fragment layout.
// tri_f[((h*16 + mtile)*32 + jtile)*32 + lane] (float4):
//   {tri[q0][j0], tri[q0][j0+1], tri[q0+8][j0], tri[q0+8][j0+1]}
//   q0 = mtile*16 + (lane>>2), j0 = jtile*8 + (lane&3)*2
// One warp per (h, mtile, jtile): coalesced 512B stores.
// ---------------------------------------------------------------------------
__global__ __launch_bounds__(256) void k_trif()
{
    int wid  = blockIdx.x * 8 + (threadIdx.x >> 5);   // 0..2047
    int lane = threadIdx.x & 31;
    int h     = wid >> 9;           // 512 tiles per head
    int tile  = wid & 511;
    int mtile = tile >> 5;
    int jtile = tile & 31;
    int q0 = mtile*16 + (lane >> 2);
    int j0 = jtile*8  + (lane & 3)*2;
    const float* tr = g_tri + (size_t)h*NPOS;
    float4 o;
    o.x = tr[(size_t)q0*NN + j0];
    o.y = tr[(size_t)q0*NN + j0 + 1];
    o.z = tr[(size_t)(q0+8)*NN + j0];
    o.w = tr[(size_t)(q0+8)*NN + j0 + 1];
    *(float4*)(g_trif + ((size_t)wid*32 + lane)*4) = o;
}

// ---------------------------------------------------------------------------
// tf32 GEMM 128x128, 8 warps, cp.async double buffer (verified)
// ---------------------------------------------------------------------------
#define GSTG (128*36)

__device__ __forceinline__ void gemm_stage(
    const uint32_t* __restrict__ A, const uint32_t* __restrict__ W,
    uint32_t* as, uint32_t* ws, int p0, int c0, int t)
{
    #pragma unroll
    for (int i = 0; i < 4; i++) {
        int idx = t + i*256;
        int row = idx >> 3;
        int cs  = idx & 7;
        cp16(as + row*36 + cs*4, A + (size_t)(p0+row)*CZ + c0 + cs*4);
        cp16(ws + row*36 + cs*4, W + (size_t)row*CZ + c0 + cs*4);
    }
}

__device__ __forceinline__ void gemm_tile(
    const uint32_t* __restrict__ A,
    const uint32_t* __restrict__ W,
    float* __restrict__ outf,
    uint32_t* __restrict__ outt,
    const float* __restrict__ bias,
    int act, int p0)
{
    extern __shared__ uint32_t dyn[];
    int t    = threadIdx.x;
    int warp = t >> 5;
    int lane = t & 31;
    int gq   = lane >> 2;
    int tq   = lane & 3;
    int wm   = (warp >> 2) * 64;
    int wn   = (warp & 3) * 32;

    float acc[4][4][4];
    #pragma unroll
    for (int mi = 0; mi < 4; mi++)
        #pragma unroll
        for (int ni = 0; ni < 4; ni++)
            #pragma unroll
            for (int r = 0; r < 4; r++) acc[mi][ni][r] = 0.0f;

    gemm_stage(A, W, dyn, dyn + 2*GSTG, p0, 0, t);
    CP_COMMIT();
    CP_WAIT0();
    __syncthreads();

    for (int c = 0; c < 4; c++) {
        if (c < 3) {
            int nb = (c+1) & 1;
            gemm_stage(A, W, dyn + nb*GSTG, dyn + 2*GSTG + nb*GSTG,
                       p0, (c+1)*32, t);
            CP_COMMIT();
        }
        const uint32_t* as = dyn + (c&1)*GSTG;
        const uint32_t* ws = dyn + 2*GSTG + (c&1)*GSTG;

        #pragma unroll
        for (int ks = 0; ks < 4; ks++) {
            int kb = ks * 8;
            uint32_t afr[4][4], bfr[4][2];
            #pragma unroll
            for (int mi = 0; mi < 4; mi++) {
                int r = wm + mi*16 + gq;
                afr[mi][0] = as[r*36     + kb+tq];
                afr[mi][1] = as[(r+8)*36 + kb+tq];
                afr[mi][2] = as[r*36     + kb+tq+4];
                afr[mi][3] = as[(r+8)*36 + kb+tq+4];
            }
            #pragma unroll
            for (int ni = 0; ni < 4; ni++) {
                int n = wn + ni*8 + gq;
                bfr[ni][0] = ws[n*36 + kb+tq];
                bfr[ni][1] = ws[n*36 + kb+tq+4];
            }
            #pragma unroll
            for (int mi = 0; mi < 4; mi++)
                #pragma unroll
                for (int ni = 0; ni < 4; ni++)
                    mma_tf32(acc[mi][ni], afr[mi], bfr[ni]);
        }
        if (c < 3) {
            CP_WAIT0();
            __syncthreads();
        }
    }

    #pragma unroll
    for (int mi = 0; mi < 4; mi++) {
        #pragma unroll
        for (int ni = 0; ni < 4; ni++) {
            int col = wn + ni*8 + tq*2;
            float b0 = 0.f, b1 = 0.f;
            if (act) { b0 = bias[col]; b1 = bias[col+1]; }
            #pragma unroll
            for (int rr = 0; rr < 2; rr++) {
                int pos = p0 + wm + mi*16 + gq + rr*8;
                float vx = acc[mi][ni][rr*2+0];
                float vy = acc[mi][ni][rr*2+1];
                if (act == 0) {
                    *(uint2*)(outt + (size_t)pos*CZ + col) =
                        make_uint2(f2tf32(vx), f2tf32(vy));
                } else if (act == 1) {
                    vx = 1.0f/(1.0f + __expf(-(vx + b0)));
                    vy = 1.0f/(1.0f + __expf(-(vy + b1)));
                    *(float2*)(outf + (size_t)pos*CZ + col) = make_float2(vx, vy);
                } else {
                    *(float2*)(outf + (size_t)pos*CZ + col) =
                        make_float2(vx + b0, vy + b1);
                }
            }
        }
    }
}

__global__ __launch_bounds__(256, 2) void k_proj(const float* __restrict__ bg)
{
    int sel = blockIdx.y;
    const uint32_t* W = g_wt + (size_t)sel*CZ*CZ;
    uint32_t* outt = (sel==0) ? g_q : (sel==1) ? g_k : (sel==2) ? g_v : nullptr;
    gemm_tile(g_xn, W, g_g, outt, bg, (sel==3) ? 1 : 0, blockIdx.x * 128);
}

__global__ __launch_bounds__(256, 2) void k_outp(
    const float* __restrict__ bo, float* __restrict__ out)
{
    gemm_tile(g_o, g_wt + (size_t)4*CZ*CZ, out, nullptr, bo, 2, blockIdx.x * 128);
}

// ---------------------------------------------------------------------------
// K3: tensor-core attention v4.
// CTA = 128 threads (4 warps x 32 q-rows), grid (NN, 2, H).
// - log2e pre-folded; p = ex2(sacc + trif + mb), no max-sub.
// - tri via fragment-permuted g_trif: 1 coalesced LDG.128 per (mi,ni).
// - j-block of 64 processed in two ni-halves (sacc 32 regs, not 64).
// - P -> A-frag via quad shuffles; __launch_bounds__(128,4) for 4 CTA/SM.
// ---------------------------------------------------------------------------
#define KVSTG (64*36)

__global__ __launch_bounds__(128, 4) void k_attn(const float* __restrict__ mask)
{
    __shared__ uint32_t kvbuf[4*KVSTG];   // K[2] | V[2]
    __shared__ float mb_s[256];

    int i  = blockIdx.x;
    int q0 = blockIdx.y * 128;
    int h  = blockIdx.z;
    int t = threadIdx.x;
    int warp = t >> 5, lane = t & 31;
    int gq = lane >> 2, tq = lane & 3;
    int wrow = q0 + warp * 32;

    mb_s[t]       = LOG2E * 1e9f * (mask[i*NN + t] - 1.0f);
    mb_s[t + 128] = LOG2E * 1e9f * (mask[i*NN + t + 128] - 1.0f);

    uint32_t* kb[2] = { kvbuf,           kvbuf + KVSTG };
    uint32_t* vb[2] = { kvbuf + 2*KVSTG, kvbuf + 3*KVSTG };

    // stage K/V for jb=0
    #pragma unroll
    for (int it = 0; it < 4; it++) {
        int idx = t + it*128;
        int row = idx >> 3, c4 = idx & 7;
        size_t gb = ((size_t)(i*NN + row))*CZ + h*DH + c4*4;
        cp16(&kb[0][row*36 + c4*4], g_k + gb);
        cp16(&vb[0][row*36 + c4*4], g_v + gb);
    }
    CP_COMMIT();

    // Q fragments via direct LDG (scale*log2e folded into wq)
    uint32_t qf[2][4][4];
    #pragma unroll
    for (int mi = 0; mi < 2; mi++) {
        const uint32_t* qr0 = g_q + ((size_t)(i*NN + wrow + mi*16 + gq))*CZ + h*DH;
        const uint32_t* qr8 = qr0 + 8*CZ;
        #pragma unroll
        for (int ks = 0; ks < 4; ks++) {
            qf[mi][ks][0] = qr0[ks*8 + tq];
            qf[mi][ks][1] = qr8[ks*8 + tq];
            qf[mi][ks][2] = qr0[ks*8 + tq + 4];
            qf[mi][ks][3] = qr8[ks*8 + tq + 4];
        }
    }

    float lrun[2][2] = {{0.f,0.f},{0.f,0.f}};
    float oacc[2][4][4];
    #pragma unroll
    for (int mi = 0; mi < 2; mi++)
        #pragma unroll
        for (int nd = 0; nd < 4; nd++)
            #pragma unroll
            for (int r = 0; r < 4; r++) oacc[mi][nd][r] = 0.0f;

    // fragment-layout tri base: ((h*16 + mtile)*32 + jtile)*32 + lane
    int mtile0 = wrow >> 4;
    const float4* tf = (const float4*)g_trif;

    CP_WAIT0();
    __syncthreads();

    int srcA = (lane & ~3) | (tq >> 1);
    bool odd = (tq & 1);

    for (int jb = 0; jb < 4; jb++) {
        int j0 = jb * 64;
        int cur = jb & 1;
        if (jb < 3) {
            int nxt = (jb+1) & 1;
            #pragma unroll
            for (int it = 0; it < 4; it++) {
                int idx = t + it*128;
                int row = idx >> 3, c4 = idx & 7;
                size_t gb = ((size_t)(i*NN + j0 + 64 + row))*CZ + h*DH + c4*4;
                cp16(&kb[nxt][row*36 + c4*4], g_k + gb);
                cp16(&vb[nxt][row*36 + c4*4], g_v + gb);
            }
            CP_COMMIT();
        }
        const uint32_t* k_s = kb[cur];
        const uint32_t* v_s = vb[cur];

        #pragma unroll
        for (int half = 0; half < 2; half++) {
            int jh = half * 32;

            // S = Q K^T for this 32-key half
            float sacc[2][4][4];
            #pragma unroll
            for (int mi = 0; mi < 2; mi++)
                #pragma unroll
                for (int ni = 0; ni < 4; ni++)
                    #pragma unroll
                    for (int r = 0; r < 4; r++) sacc[mi][ni][r] = 0.0f;

            #pragma unroll
            for (int ks = 0; ks < 4; ks++) {
                uint32_t bf[4][2];
                #pragma unroll
                for (int ni = 0; ni < 4; ni++) {
                    int base = (jh + ni*8 + gq)*36 + ks*8 + tq;
                    bf[ni][0] = k_s[base];
                    bf[ni][1] = k_s[base + 4];
                }
                #pragma unroll
                for (int mi = 0; mi < 2; mi++)
                    #pragma unroll
                    for (int ni = 0; ni < 4; ni++)
                        mma_tf32(sacc[mi][ni], qf[mi][ks], bf[ni]);
            }

            // p = ex2(sacc + trif + mb); accumulate l
            #pragma unroll
            for (int mi = 0; mi < 2; mi++) {
                float la0 = 0.f, la1 = 0.f;
                #pragma unroll
                for (int ni = 0; ni < 4; ni++) {
                    int jtile = jb*8 + half*4 + ni;
                    float4 tv = tf[((h*16 + mtile0 + mi)*32 + jtile)*32 + lane];
                    int j = j0 + jh + ni*8 + tq*2;
                    float mb0 = mb_s[j], mb1 = mb_s[j+1];
                    float p0 = ex2f(sacc[mi][ni][0] + (tv.x + mb0));
                    float p1 = ex2f(sacc[mi][ni][1] + (tv.y + mb1));
                    float p2 = ex2f(sacc[mi][ni][2] + (tv.z + mb0));
                    float p3 = ex2f(sacc[mi][ni][3] + (tv.w + mb1));
                    uint32_t u0 = f2tf32(p0), u1 = f2tf32(p1);
                    uint32_t u2 = f2tf32(p2), u3 = f2tf32(p3);
                    sacc[mi][ni][0] = __uint_as_float(u0);
                    sacc[mi][ni][1] = __uint_as_float(u1);
                    sacc[mi][ni][2] = __uint_as_float(u2);
                    sacc[mi][ni][3] = __uint_as_float(u3);
                    la0 += __uint_as_float(u0) + __uint_as_float(u1);
                    la1 += __uint_as_float(u2) + __uint_as_float(u3);
                }
                lrun[mi][0] += la0; lrun[mi][1] += la1;
            }

            // O += P V (k = 32 keys of this half)
            #pragma unroll
            for (int ks2 = 0; ks2 < 4; ks2++) {
                uint32_t bf[4][2];
                #pragma unroll
                for (int nd = 0; nd < 4; nd++) {
                    bf[nd][0] = v_s[(jh + ks2*8 + tq)*36     + nd*8 + gq];
                    bf[nd][1] = v_s[(jh + ks2*8 + tq + 4)*36 + nd*8 + gq];
                }
                #pragma unroll
                for (int mi = 0; mi < 2; mi++) {
                    float c0 = sacc[mi][ks2][0], c1 = sacc[mi][ks2][1];
                    float c2 = sacc[mi][ks2][2], c3 = sacc[mi][ks2][3];
                    float l0a = __shfl_sync(0xffffffffu, c0, srcA);
                    float h0a = __shfl_sync(0xffffffffu, c1, srcA);
                    float l1a = __shfl_sync(0xffffffffu, c2, srcA);
                    float h1a = __shfl_sync(0xffffffffu, c3, srcA);
                    float l0b = __shfl_sync(0xffffffffu, c0, srcA+2);
                    float h0b = __shfl_sync(0xffffffffu, c1, srcA+2);
                    float l1b = __shfl_sync(0xffffffffu, c2, srcA+2);
                    float h1b = __shfl_sync(0xffffffffu, c3, srcA+2);
                    uint32_t af[4];
                    af[0] = __float_as_uint(odd ? h0a : l0a);
                    af[1] = __float_as_uint(odd ? h1a : l1a);
                    af[2] = __float_as_uint(odd ? h0b : l0b);
                    af[3] = __float_as_uint(odd ? h1b : l1b);
                    #pragma unroll
                    for (int nd = 0; nd < 4; nd++)
                        mma_tf32(oacc[mi][nd], af, bf[nd]);
                }
            }
        }
        if (jb < 3) {
            CP_WAIT0();
            __syncthreads();
        }
    }

    // epilogue: normalize, gate, store tf32
    #pragma unroll
    for (int mi = 0; mi < 2; mi++) {
        float l0 = lrun[mi][0];
        l0 += __shfl_xor_sync(0xffffffffu, l0, 1);
        l0 += __shfl_xor_sync(0xffffffffu, l0, 2);
        float l1 = lrun[mi][1];
        l1 += __shfl_xor_sync(0xffffffffu, l1, 1);
        l1 += __shfl_xor_sync(0xffffffffu, l1, 2);
        float inv0 = 1.0f / l0, inv1 = 1.0f / l1;
        int r0 = wrow + mi*16 + gq;
        #pragma unroll
        for (int nd = 0; nd < 4; nd++) {
            int d = h*DH + nd*8 + tq*2;
            size_t b0 = ((size_t)(i*NN + r0))*CZ + d;
            size_t b1 = ((size_t)(i*NN + r0 + 8))*CZ + d;
            float2 gg0 = *(const float2*)(g_g + b0);
            float2 gg1 = *(const float2*)(g_g + b1);
            *(uint2*)(g_o + b0) = make_uint2(
                f2tf32(oacc[mi][nd][0]*inv0*gg0.x),
                f2tf32(oacc[mi][nd][1]*inv0*gg0.y));
            *(uint2*)(g_o + b1) = make_uint2(
                f2tf32(oacc[mi][nd][2]*inv1*gg1.x),
                f2tf32(oacc[mi][nd][3]*inv1*gg1.y));
        }
    }
}

// ---------------------------------------------------------------------------
extern "C" void kernel_launch(void* const* d_in, const int* in_sizes, int n_in,
                              void* d_out, int out_size)
{
    const float* x     = (const float*)d_in[0];
    const float* mask  = (const float*)d_in[1];
    const float* ln_g  = (const float*)d_in[2];
    const float* ln_b  = (const float*)d_in[3];
    const float* w_tri = (const float*)d_in[4];
    const float* wq    = (const float*)d_in[5];
    const float* wk    = (const float*)d_in[6];
    const float* wv    = (const float*)d_in[7];
    const float* wg    = (const float*)d_in[8];
    const float* bg    = (const float*)d_in[9];
    const float* wo    = (const float*)d_in[10];
    const float* bo    = (const float*)d_in[11];
    float* out = (float*)d_out;

    const int GEMM_SMEM = 4*GSTG*4;   // 73728 B
    cudaFuncSetAttribute(k_proj, cudaFuncAttributeMaxDynamicSharedMemorySize, GEMM_SMEM);
    cudaFuncSetAttribute(k_outp, cudaFuncAttributeMaxDynamicSharedMemorySize, GEMM_SMEM);

    k_prep<<<dim3(64, 5), 256>>>(wq, wk, wv, wg, wo);
    k_ln  <<<NPOS/8, 256>>>(x, ln_g, ln_b, w_tri);
    k_trif<<<256, 256>>>();
    k_proj<<<dim3(NPOS/128, 4), 256, GEMM_SMEM>>>(bg);
    k_attn<<<dim3(NN, 2, H), 128>>>(mask);
    k_outp<<<NPOS/128, 256, GEMM_SMEM>>>(bo, out);
}